// round 2
// baseline (speedup 1.0000x reference)
#include <cuda_runtime.h>

#define Bd   2
#define Cc   128
#define Hd   64
#define Wd   512
#define HW   (Hd*Wd)          // 32768
#define NPIX (Bd*HW)          // 65536
#define EPS  1e-5f

// Scratch (device globals: allocation-free)
__device__ float g_Y[Cc * NPIX];   // [o][gpix]  relu(bn_f(fw·feat))
__device__ float g_Q[Cc * NPIX];   // [o][gpix]  scale_p*(pw·cart)
// cparams: [0:128) scale_f, [128:256) shift_f, [256:384) scale_p,
//          [384:512) shift_p, [512:515) scale_e, [515:518) shift_e
__device__ float g_cp[520];

// ---------------------------------------------------------------- prep
__global__ void prep_kernel(const float* fg, const float* fb, const float* fm, const float* fv,
                            const float* pg, const float* pb, const float* pm, const float* pv,
                            const float* eg, const float* eb, const float* em, const float* ev) {
    int o = threadIdx.x;
    if (o < Cc) {
        float sf = fg[o] * rsqrtf(fv[o] + EPS);
        g_cp[o]        = sf;
        g_cp[128 + o]  = fb[o] - fm[o] * sf;
        float sp = pg[o] * rsqrtf(pv[o] + EPS);
        g_cp[256 + o]  = sp;
        g_cp[384 + o]  = pb[o] - pm[o] * sp;
    }
    if (o < 3) {
        float se = eg[o] * rsqrtf(ev[o] + EPS);
        g_cp[512 + o] = se;
        g_cp[515 + o] = eb[o] - em[o] * se;
    }
}

// ---------------------------------------------------------------- pass1
// grid 512 blocks x 512 threads; each block: 128 pixels x 128 out channels.
// Thread: pixel = tid&127, out-group og = tid>>7 (32 channels each).
// Weights transposed into smem [c][o] (pad 132) for broadcast float4 reads.
extern __shared__ float s_wt[];   // 128*132 floats = 67584 B

__global__ void __launch_bounds__(512, 2)
pass1_kernel(const float* __restrict__ feat, const float* __restrict__ cart,
             const float* __restrict__ fw,   const float* __restrict__ pw) {
    const int tid  = threadIdx.x;
    const int pix  = tid & 127;
    const int og   = tid >> 7;           // 0..3
    const int gp0  = blockIdx.x << 7;    // global pixel base (batch-contiguous)
    const int b    = gp0 >> 15;
    const int pb_  = gp0 & (HW - 1);

    // stage fw transposed: s_wt[c*132 + o] = fw[o*128 + c]
    for (int i = tid; i < Cc * Cc; i += 512) {
        int o = i >> 7, c = i & 127;
        s_wt[c * 132 + o] = fw[i];
    }
    __syncthreads();

    float acc[32];
#pragma unroll
    for (int j = 0; j < 32; j++) acc[j] = 0.f;

    const float* fp = feat + (size_t)b * Cc * HW + pb_ + pix;

#pragma unroll 4
    for (int c = 0; c < Cc; c++) {
        float x = __ldg(fp + c * HW);
        const float4* wr = (const float4*)(s_wt + c * 132 + (og << 5));
#pragma unroll
        for (int j = 0; j < 8; j++) {
            float4 w = wr[j];
            acc[4 * j + 0] += w.x * x;
            acc[4 * j + 1] += w.y * x;
            acc[4 * j + 2] += w.z * x;
            acc[4 * j + 3] += w.w * x;
        }
    }

    // cart for Q
    const int gp = gp0 + pix;
    const float cx = __ldg(cart + ((size_t)b * 3 + 0) * HW + pb_ + pix);
    const float cy = __ldg(cart + ((size_t)b * 3 + 1) * HW + pb_ + pix);
    const float cz = __ldg(cart + ((size_t)b * 3 + 2) * HW + pb_ + pix);

#pragma unroll
    for (int j = 0; j < 32; j++) {
        int o = (og << 5) + j;
        float sf = g_cp[o], hf = g_cp[128 + o];
        g_Y[(size_t)o * NPIX + gp] = fmaxf(sf * acc[j] + hf, 0.f);
        float sp = g_cp[256 + o];
        float q = sp * (__ldg(pw + o * 3 + 0) * cx +
                        __ldg(pw + o * 3 + 1) * cy +
                        __ldg(pw + o * 3 + 2) * cz);
        g_Q[(size_t)o * NPIX + gp] = q;
    }
}

// ---------------------------------------------------------------- pass2
// grid 512 x 128 threads, thread = one pixel. Loop all 128 channels,
// 9-neighbor branchless max (fe >= 0 so mu in {0,1} as multiplier works),
// fused ew.geo epilogue.
__global__ void __launch_bounds__(128)
pass2_kernel(const float* __restrict__ cart, const unsigned int* __restrict__ mk,
             float* __restrict__ out_geo, float* __restrict__ out_cart,
             const float* __restrict__ ew) {
    const int gp = (blockIdx.x << 7) + threadIdx.x;
    const int b  = gp >> 15;
    const int p  = gp & (HW - 1);
    const int y  = p >> 9;
    const int x  = p & (Wd - 1);

    int   off[9];
    float am[9];
#pragma unroll
    for (int kh = 0; kh < 3; kh++) {
#pragma unroll
        for (int kw = 0; kw < 3; kw++) {
            int n = kh * 3 + kw;
            int yy = y + kh - 1, xx = x + kw - 1;
            bool v = (yy >= 0) && (yy < Hd) && (xx >= 0) && (xx < Wd);
            int gpn = (b << 15) + yy * Wd + xx;
            off[n] = v ? gpn : gp;                       // safe in-bounds fallback
            am[n]  = (v && (mk[off[n]] != 0u)) ? 1.f : 0.f;
        }
    }

    float e0 = 0.f, e1 = 0.f, e2 = 0.f;

    for (int o = 0; o < Cc; o++) {
        const float* Yo = g_Y + (size_t)o * NPIX;
        const float* Qo = g_Q + (size_t)o * NPIX;
        const float qc = Qo[gp];
        const float hp = g_cp[384 + o];
        float gm = 0.f;
#pragma unroll
        for (int n = 0; n < 9; n++) {
            float fe = Yo[off[n]] + fmaxf(Qo[off[n]] - qc + hp, 0.f);
            gm = fmaxf(gm, am[n] * fe);
        }
        out_geo[((size_t)b * Cc + o) * HW + p] = gm;
        e0 += __ldg(ew + 0 * Cc + o) * gm;
        e1 += __ldg(ew + 1 * Cc + o) * gm;
        e2 += __ldg(ew + 2 * Cc + o) * gm;
    }

    const float mc = (mk[gp] != 0u) ? 1.f : 0.f;
    float e[3] = {e0, e1, e2};
#pragma unroll
    for (int k = 0; k < 3; k++) {
        float v = g_cp[512 + k] * e[k] + g_cp[515 + k];
        size_t ci = ((size_t)b * 3 + k) * HW + p;
        out_cart[ci] = cart[ci] + v * mc;
    }
}

// ---------------------------------------------------------------- launch
extern "C" void kernel_launch(void* const* d_in, const int* in_sizes, int n_in,
                              void* d_out, int out_size) {
    const float* feat = (const float*)d_in[0];
    const float* cart = (const float*)d_in[1];
    const unsigned int* mask = (const unsigned int*)d_in[2];
    const float* pw = (const float*)d_in[3];
    const float* pg = (const float*)d_in[4];
    const float* pb = (const float*)d_in[5];
    const float* pm = (const float*)d_in[6];
    const float* pv = (const float*)d_in[7];
    const float* fw = (const float*)d_in[8];
    const float* fg = (const float*)d_in[9];
    const float* fb = (const float*)d_in[10];
    const float* fm = (const float*)d_in[11];
    const float* fv = (const float*)d_in[12];
    const float* ew = (const float*)d_in[13];
    const float* eg = (const float*)d_in[14];
    const float* eb = (const float*)d_in[15];
    const float* em = (const float*)d_in[16];
    const float* ev = (const float*)d_in[17];

    float* out_geo  = (float*)d_out;                       // (B,128,H,W)
    float* out_cart = (float*)d_out + (size_t)Bd * Cc * HW; // (B,3,H,W)

    static int smem_set = -1;
    const int smem_bytes = Cc * 132 * sizeof(float);
    // idempotent, host-side attribute set (not a stream op, not an allocation)
    cudaFuncSetAttribute(pass1_kernel, cudaFuncAttributeMaxDynamicSharedMemorySize, smem_bytes);
    (void)smem_set; (void)in_sizes; (void)n_in; (void)out_size;

    prep_kernel<<<1, 128>>>(fg, fb, fm, fv, pg, pb, pm, pv, eg, eb, em, ev);
    pass1_kernel<<<NPIX / 128, 512, smem_bytes>>>(feat, cart, fw, pw);
    pass2_kernel<<<NPIX / 128, 128>>>(cart, mask, out_geo, out_cart, ew);
}

// round 3
// speedup vs baseline: 2.1570x; 2.1570x over previous
#include <cuda_runtime.h>

#define Bd   2
#define Cc   128
#define Hd   64
#define Wd   512
#define HW   (Hd*Wd)          // 32768
#define NPIX (Bd*HW)          // 65536
#define EPS  1e-5f

// ---------------- device scratch (allocation-free) ----------------
__device__ float  g_Y [Cc * NPIX];   // [o][gp] relu(bn_f(fw·feat))
__device__ float  g_WT[Cc * Cc];     // [c][o]  fw^T with scale_f folded in
__device__ float  g_hf[Cc];          // shift_f
__device__ float4 g_pw4[Cc];         // {pw0*sp, pw1*sp, pw2*sp, hp}
__device__ float4 g_ew4[Cc];         // {ew0*se0, ew1*se1, ew2*se2, 0}
__device__ float  g_she[3];          // shift_e

// ---------------------------------------------------------------- prep
// blocks 0..31: transpose+scale fw into g_WT.  block 32: fold BN params.
__global__ void prep_kernel(const float* __restrict__ fw,
                            const float* __restrict__ fg, const float* __restrict__ fb,
                            const float* __restrict__ fm, const float* __restrict__ fv,
                            const float* __restrict__ pw,
                            const float* __restrict__ pg, const float* __restrict__ pb,
                            const float* __restrict__ pm, const float* __restrict__ pv,
                            const float* __restrict__ ew,
                            const float* __restrict__ eg, const float* __restrict__ eb,
                            const float* __restrict__ em, const float* __restrict__ ev) {
    const int tid = threadIdx.x;
    if (blockIdx.x < 32) {
        // coalesced read of fw[o][c]; scattered write g_WT[c][o]
#pragma unroll
        for (int t = 0; t < 2; t++) {
            int i = (blockIdx.x << 9) + (t << 8) + tid;   // 0..16383
            int o = i >> 7, c = i & 127;
            float sf = fg[o] * rsqrtf(fv[o] + EPS);
            g_WT[c * Cc + o] = fw[i] * sf;
        }
    } else if (tid < Cc) {
        int o = tid;
        float sf = fg[o] * rsqrtf(fv[o] + EPS);
        g_hf[o] = fb[o] - fm[o] * sf;
        float sp = pg[o] * rsqrtf(pv[o] + EPS);
        float hp = pb[o] - pm[o] * sp;
        g_pw4[o] = make_float4(pw[3*o]*sp, pw[3*o+1]*sp, pw[3*o+2]*sp, hp);
        float se0 = eg[0] * rsqrtf(ev[0] + EPS);
        float se1 = eg[1] * rsqrtf(ev[1] + EPS);
        float se2 = eg[2] * rsqrtf(ev[2] + EPS);
        g_ew4[o] = make_float4(ew[o]*se0, ew[Cc+o]*se1, ew[2*Cc+o]*se2, 0.f);
        if (o < 3) {
            float se = eg[o] * rsqrtf(ev[o] + EPS);
            g_she[o] = eb[o] - em[o] * se;
        }
    }
}

// ---------------------------------------------------------------- pass1
// Register-tiled GEMM: Y[128 out][NPIX] = relu(WT^T x F + hf)
// 256 threads, block tile 128(out) x 128(px), K chunks of 16, double-buffered.
// Each thread: 8x8 micro-tile (4+4 split in both dims).
#define KC 16
__global__ void __launch_bounds__(256, 2)
pass1_kernel(const float* __restrict__ feat) {
    __shared__ float Fs[2][KC][128];
    __shared__ float Ws[2][KC][128];

    const int tid = threadIdx.x;
    const int tx  = tid & 15;           // pixel group
    const int ty  = tid >> 4;           // out-channel group
    const int gp0 = blockIdx.x << 7;
    const int b   = gp0 >> 15;
    const int p0  = gp0 & (HW - 1);

    const float* fbase = feat + b * Cc * HW + p0;   // row c: fbase + c*HW
    const int k0 = tid >> 5;           // 0..7
    const int j4 = (tid & 31) << 2;    // 0..124

    // ---- load chunk 0 ----
    {
        float4 f0 = *(const float4*)(fbase + k0 * HW + j4);
        float4 f1 = *(const float4*)(fbase + (k0 + 8) * HW + j4);
        float4 w0 = *(const float4*)(g_WT + k0 * Cc + j4);
        float4 w1 = *(const float4*)(g_WT + (k0 + 8) * Cc + j4);
        *(float4*)&Fs[0][k0][j4]     = f0;
        *(float4*)&Fs[0][k0 + 8][j4] = f1;
        *(float4*)&Ws[0][k0][j4]     = w0;
        *(float4*)&Ws[0][k0 + 8][j4] = w1;
    }
    __syncthreads();

    float acc[8][8];
#pragma unroll
    for (int i = 0; i < 8; i++)
#pragma unroll
        for (int j = 0; j < 8; j++) acc[i][j] = 0.f;

    const int pA = tx << 2, pB = 64 + (tx << 2);
    const int oA = ty << 2, oB = 64 + (ty << 2);

    for (int ch = 0; ch < Cc / KC; ch++) {
        const int cur = ch & 1;
        float4 pf0, pf1, pw0, pw1;
        if (ch < Cc / KC - 1) {
            const int c0n = (ch + 1) * KC;
            pf0 = *(const float4*)(fbase + (c0n + k0) * HW + j4);
            pf1 = *(const float4*)(fbase + (c0n + k0 + 8) * HW + j4);
            pw0 = *(const float4*)(g_WT + (c0n + k0) * Cc + j4);
            pw1 = *(const float4*)(g_WT + (c0n + k0 + 8) * Cc + j4);
        }
#pragma unroll
        for (int k = 0; k < KC; k++) {
            float4 fA = *(float4*)&Fs[cur][k][pA];
            float4 fB = *(float4*)&Fs[cur][k][pB];
            float4 wA = *(float4*)&Ws[cur][k][oA];
            float4 wB = *(float4*)&Ws[cur][k][oB];
            float fr[8] = {fA.x, fA.y, fA.z, fA.w, fB.x, fB.y, fB.z, fB.w};
            float wr[8] = {wA.x, wA.y, wA.z, wA.w, wB.x, wB.y, wB.z, wB.w};
#pragma unroll
            for (int i = 0; i < 8; i++)
#pragma unroll
                for (int j = 0; j < 8; j++)
                    acc[i][j] += wr[i] * fr[j];
        }
        __syncthreads();
        if (ch < Cc / KC - 1) {
            const int nxt = cur ^ 1;
            *(float4*)&Fs[nxt][k0][j4]     = pf0;
            *(float4*)&Fs[nxt][k0 + 8][j4] = pf1;
            *(float4*)&Ws[nxt][k0][j4]     = pw0;
            *(float4*)&Ws[nxt][k0 + 8][j4] = pw1;
            __syncthreads();
        }
    }

    // ---- epilogue: relu(acc + hf[o]) -> g_Y ----
#pragma unroll
    for (int i = 0; i < 8; i++) {
        int o  = (i < 4) ? (oA + i) : (oB + i - 4);
        float hf = g_hf[o];
        float* yo = g_Y + o * NPIX + gp0;
        float4 vA = make_float4(fmaxf(acc[i][0] + hf, 0.f), fmaxf(acc[i][1] + hf, 0.f),
                                fmaxf(acc[i][2] + hf, 0.f), fmaxf(acc[i][3] + hf, 0.f));
        float4 vB = make_float4(fmaxf(acc[i][4] + hf, 0.f), fmaxf(acc[i][5] + hf, 0.f),
                                fmaxf(acc[i][6] + hf, 0.f), fmaxf(acc[i][7] + hf, 0.f));
        *(float4*)(yo + pA) = vA;
        *(float4*)(yo + pB) = vB;
    }
}

// ---------------------------------------------------------------- pass2
// thread = pixel. 9-neighbor max with pos recomputed from relative coords
// (3 FMA each) instead of loading Q. Fused ew epilogue.
__global__ void __launch_bounds__(128)
pass2_kernel(const float* __restrict__ cart, const unsigned int* __restrict__ mk,
             float* __restrict__ out_geo, float* __restrict__ out_cart) {
    __shared__ float4 s_pw[Cc];
    __shared__ float4 s_ew[Cc];
    {
        int t = threadIdx.x;
        s_pw[t] = g_pw4[t];
        s_ew[t] = g_ew4[t];
    }
    __syncthreads();

    const int gp = (blockIdx.x << 7) + threadIdx.x;
    const int b  = gp >> 15;
    const int p  = gp & (HW - 1);
    const int y  = p >> 9;
    const int x  = p & (Wd - 1);

    const float* cb = cart + b * 3 * HW;
    const float ccx = __ldg(cb + p);
    const float ccy = __ldg(cb + HW + p);
    const float ccz = __ldg(cb + 2 * HW + p);

    int   off[9];
    float am[9], rx[9], ry[9], rz[9];
#pragma unroll
    for (int kh = 0; kh < 3; kh++) {
#pragma unroll
        for (int kw = 0; kw < 3; kw++) {
            int n = kh * 3 + kw;
            int yy = y + kh - 1, xx = x + kw - 1;
            bool v = (yy >= 0) && (yy < Hd) && (xx >= 0) && (xx < Wd);
            int pn = yy * Wd + xx;
            int o  = v ? ((b << 15) + pn) : gp;
            off[n] = o;
            am[n]  = (v && (__ldg(mk + o) != 0u)) ? 1.f : 0.f;
            int pl = o & (HW - 1);
            rx[n] = __ldg(cb + pl) - ccx;
            ry[n] = __ldg(cb + HW + pl) - ccy;
            rz[n] = __ldg(cb + 2 * HW + pl) - ccz;
        }
    }

    float e0 = 0.f, e1 = 0.f, e2 = 0.f;
    float* og = out_geo + b * Cc * HW + p;

#pragma unroll 2
    for (int o = 0; o < Cc; o++) {
        float4 pwv = s_pw[o];
        const float* Yo = g_Y + o * NPIX;
        float gm = 0.f;
#pragma unroll
        for (int n = 0; n < 9; n++) {
            float pos = fmaxf(pwv.x * rx[n] + pwv.y * ry[n] + pwv.z * rz[n] + pwv.w, 0.f);
            float fe  = __ldg(Yo + off[n]) + pos;
            gm = fmaxf(gm, am[n] * fe);
        }
        og[o * HW] = gm;
        float4 e = s_ew[o];
        e0 += e.x * gm; e1 += e.y * gm; e2 += e.z * gm;
    }

    const float mc = (__ldg(mk + gp) != 0u) ? 1.f : 0.f;
    float ev[3] = {e0, e1, e2};
#pragma unroll
    for (int k = 0; k < 3; k++) {
        int ci = (b * 3 + k) * HW + p;
        out_cart[ci] = __ldg(cart + ci) + (ev[k] + g_she[k]) * mc;
    }
}

// ---------------------------------------------------------------- launch
extern "C" void kernel_launch(void* const* d_in, const int* in_sizes, int n_in,
                              void* d_out, int out_size) {
    const float* feat = (const float*)d_in[0];
    const float* cart = (const float*)d_in[1];
    const unsigned int* mask = (const unsigned int*)d_in[2];
    const float* pw = (const float*)d_in[3];
    const float* pg = (const float*)d_in[4];
    const float* pb = (const float*)d_in[5];
    const float* pm = (const float*)d_in[6];
    const float* pv = (const float*)d_in[7];
    const float* fw = (const float*)d_in[8];
    const float* fg = (const float*)d_in[9];
    const float* fb = (const float*)d_in[10];
    const float* fm = (const float*)d_in[11];
    const float* fv = (const float*)d_in[12];
    const float* ew = (const float*)d_in[13];
    const float* eg = (const float*)d_in[14];
    const float* eb = (const float*)d_in[15];
    const float* em = (const float*)d_in[16];
    const float* ev = (const float*)d_in[17];
    (void)in_sizes; (void)n_in; (void)out_size;

    float* out_geo  = (float*)d_out;                        // (B,128,H,W)
    float* out_cart = (float*)d_out + (size_t)Bd * Cc * HW; // (B,3,H,W)

    prep_kernel<<<33, 256>>>(fw, fg, fb, fm, fv, pw, pg, pb, pm, pv,
                             ew, eg, eb, em, ev);
    pass1_kernel<<<NPIX / 128, 256>>>(feat);
    pass2_kernel<<<NPIX / 128, 128>>>(cart, mask, out_geo, out_cart);
}